// round 6
// baseline (speedup 1.0000x reference)
#include <cuda_runtime.h>
#include <math.h>

#define L_SEQ 4096
#define EDIM  512
#define HDIM  1024
#define G3    3072   // 3*HDIM
#define NCTA  128

// ---------------- scratch (static device globals; no allocation) -------------
__device__ float g_emb[(size_t)L_SEQ * EDIM];          // 8 MB
__device__ float g_gi [(size_t)L_SEQ * G3];            // 50 MB (reused per layer)
__device__ float g_ys [(size_t)L_SEQ * HDIM];          // 16 MB (layer-0 outputs)
__device__ float g_hv[2][HDIM];                        // double-buffered hidden state

// 8 counter replicas, one 128B line each; warp w polls replica w.
struct __align__(128) CtrLine { unsigned v; unsigned pad[31]; };
__device__ CtrLine g_ctr8[8];

// ---------------- memory-model helpers ---------------------------------------
__device__ __forceinline__ unsigned ldacq_u32(const unsigned* p)
{
    unsigned v;
    asm volatile("ld.acquire.gpu.global.b32 %0, [%1];" : "=r"(v) : "l"(p) : "memory");
    return v;
}
__device__ __forceinline__ void red_release_add(unsigned* p, unsigned v)
{
    asm volatile("red.release.gpu.global.add.u32 [%0], %1;" :: "l"(p), "r"(v) : "memory");
}
__device__ __forceinline__ float4 ldacq_v4(const float* p)
{
    float4 v;
    asm volatile("ld.acquire.gpu.global.v4.f32 {%0,%1,%2,%3}, [%4];"
                 : "=f"(v.x), "=f"(v.y), "=f"(v.z), "=f"(v.w) : "l"(p) : "memory");
    return v;
}
__device__ __forceinline__ float ldrelax_f32(const float* p)
{
    float v;
    asm volatile("ld.relaxed.gpu.global.f32 %0, [%1];" : "=f"(v) : "l"(p) : "memory");
    return v;
}

// ---------------- packed f32x2 helpers (sm_103a) ------------------------------
__device__ __forceinline__ unsigned long long pack2(float x, float y)
{
    unsigned long long r;
    asm("mov.b64 %0, {%1, %2};" : "=l"(r) : "f"(x), "f"(y));
    return r;
}
__device__ __forceinline__ unsigned long long fma2(unsigned long long a,
                                                   unsigned long long b,
                                                   unsigned long long c)
{
    unsigned long long d;
    asm("fma.rn.f32x2 %0, %1, %2, %3;" : "=l"(d) : "l"(a), "l"(b), "l"(c));
    return d;
}
__device__ __forceinline__ float2 unpack2(unsigned long long v)
{
    float2 f;
    asm("mov.b64 {%0, %1}, %2;" : "=f"(f.x), "=f"(f.y) : "l"(v));
    return f;
}

// fast saturation-safe activations (budget 1e-3; these are ~1e-6)
__device__ __forceinline__ float fsig(float x)
{
    return __fdividef(1.0f, 1.0f + __expf(-x));
}
__device__ __forceinline__ float ftanh(float x)
{
    return 1.0f - __fdividef(2.0f, 1.0f + __expf(2.0f * x));
}

// ---------------- embedding + max-norm --------------------------------------
__global__ void embed_kernel(const int* __restrict__ idx,
                             const float* __restrict__ E,
                             float* __restrict__ emb)
{
    int t = blockIdx.x;
    int id = idx[t];
    const float4* row = (const float4*)(E + (size_t)id * EDIM);
    float4 v = row[threadIdx.x];
    float ss = v.x*v.x + v.y*v.y + v.z*v.z + v.w*v.w;
    #pragma unroll
    for (int o = 16; o; o >>= 1) ss += __shfl_xor_sync(0xffffffffu, ss, o);
    __shared__ float red[4];
    int w = threadIdx.x >> 5;
    if ((threadIdx.x & 31) == 0) red[w] = ss;
    __syncthreads();
    float tot = red[0] + red[1] + red[2] + red[3];
    float scale = fminf(1.0f, 1.0f / fmaxf(sqrtf(tot), 1e-7f));
    v.x *= scale; v.y *= scale; v.z *= scale; v.w *= scale;
    ((float4*)(emb + (size_t)t * EDIM))[threadIdx.x] = v;
}

// ---------------- fp32 GEMM (f32x2 inner): C = A @ B^T + bias ----------------
__global__ void __launch_bounds__(256) gemm_tn(const float* __restrict__ A,
                                               const float* __restrict__ B,
                                               const float* __restrict__ bias,
                                               float* __restrict__ C,
                                               int M, int N, int K)
{
    __shared__ float As[16][128];
    __shared__ float Bs[16][136];

    int tid = threadIdx.x;
    int bm = blockIdx.y * 128;
    int bn = blockIdx.x * 128;
    int tx = tid & 15;
    int ty = tid >> 4;

    unsigned long long acc2[8][4];
    #pragma unroll
    for (int i = 0; i < 8; i++)
        #pragma unroll
        for (int j = 0; j < 4; j++) acc2[i][j] = 0ull;

    const float* Ab = A + (size_t)bm * K;
    const float* Bb = B + (size_t)bn * K;

    for (int k0 = 0; k0 < K; k0 += 16) {
        #pragma unroll
        for (int i = 0; i < 2; i++) {
            int q   = tid + i * 256;
            int row = q >> 2;
            int c4  = q & 3;
            float4 a = *(const float4*)(Ab + (size_t)row * K + k0 + c4 * 4);
            As[c4*4+0][row] = a.x; As[c4*4+1][row] = a.y;
            As[c4*4+2][row] = a.z; As[c4*4+3][row] = a.w;
            float4 b = *(const float4*)(Bb + (size_t)row * K + k0 + c4 * 4);
            Bs[c4*4+0][row] = b.x; Bs[c4*4+1][row] = b.y;
            Bs[c4*4+2][row] = b.z; Bs[c4*4+3][row] = b.w;
        }
        __syncthreads();
        #pragma unroll
        for (int k = 0; k < 16; k++) {
            float4 a0 = *(const float4*)&As[k][ty*8];
            float4 a1 = *(const float4*)&As[k][ty*8+4];
            float4 b0 = *(const float4*)&Bs[k][tx*8];
            float4 b1 = *(const float4*)&Bs[k][tx*8+4];
            float av[8] = {a0.x,a0.y,a0.z,a0.w,a1.x,a1.y,a1.z,a1.w};
            unsigned long long bp[4] = { pack2(b0.x,b0.y), pack2(b0.z,b0.w),
                                         pack2(b1.x,b1.y), pack2(b1.z,b1.w) };
            #pragma unroll
            for (int i = 0; i < 8; i++) {
                unsigned long long ad = pack2(av[i], av[i]);
                #pragma unroll
                for (int j = 0; j < 4; j++)
                    acc2[i][j] = fma2(ad, bp[j], acc2[i][j]);
            }
        }
        __syncthreads();
    }

    float bb[8];
    #pragma unroll
    for (int j = 0; j < 8; j++) bb[j] = bias[bn + tx*8 + j];
    #pragma unroll
    for (int i = 0; i < 8; i++) {
        size_t row = (size_t)(bm + ty*8 + i);
        float2 c0 = unpack2(acc2[i][0]);
        float2 c1 = unpack2(acc2[i][1]);
        float2 c2 = unpack2(acc2[i][2]);
        float2 c3 = unpack2(acc2[i][3]);
        float4 o0 = make_float4(c0.x+bb[0], c0.y+bb[1], c1.x+bb[2], c1.y+bb[3]);
        float4 o1 = make_float4(c2.x+bb[4], c2.y+bb[5], c3.x+bb[6], c3.y+bb[7]);
        *(float4*)(C + row * N + bn + tx*8    ) = o0;
        *(float4*)(C + row * N + bn + tx*8 + 4) = o1;
    }
}

// ---------------- persistent GRU recurrence (register-direct h, replica ctrs) -
// 128 CTAs x 256 threads. Warp w of CTA b owns unit b*8+w; W_hh in registers
// as f32x2 pairs. Per step:
//   - warp polls its own counter replica (8 lines chip-wide, read-broadcast)
//   - warp loads FULL h vector straight to registers: 8 coalesced 128-bit
//     gpu-scope loads (no smem staging, no top-of-step barriers)
//   - FMA2 chain + xor-shfl reduce + all-lane gate math
//   - lane0 stores h'; ONE __syncthreads; tids 0..7 red.release the 8 replicas
// Buffer-reuse safety: identical induction to R4 (ctr>=128t => all CTAs
// finished step t-1 => buffer parity (t+1)&1 has no step-(t-1) readers left).
__global__ void __launch_bounds__(256, 1) gru_scan(const float* __restrict__ Whh,
                                                   const float* __restrict__ bhh,
                                                   const float* __restrict__ gi,
                                                   float* __restrict__ ys,
                                                   float* __restrict__ hfin,
                                                   float* __restrict__ hfin2,
                                                   int T)
{
    int tid  = threadIdx.x;
    int w    = tid >> 5;
    int lane = tid & 31;
    int b    = blockIdx.x;
    int unit = b * 8 + w;

    const ulonglong2* Wr = (const ulonglong2*)(Whh + (size_t)unit            * HDIM);
    const ulonglong2* Wz = (const ulonglong2*)(Whh + (size_t)(HDIM   + unit) * HDIM);
    const ulonglong2* Wn = (const ulonglong2*)(Whh + (size_t)(2*HDIM + unit) * HDIM);
    ulonglong2 wr2[8], wz2[8], wn2[8];
    #pragma unroll
    for (int c = 0; c < 8; c++) {
        wr2[c] = Wr[c*32 + lane];
        wz2[c] = Wz[c*32 + lane];
        wn2[c] = Wn[c*32 + lane];
    }
    float br  = bhh[unit];
    float bz  = bhh[HDIM   + unit];
    float bn_ = bhh[2*HDIM + unit];

    float h_last = 0.0f;

    for (int t = 0; t < T; t++) {
        // per-warp self-discovery on its own replica line
        {
            const unsigned* slot = &g_ctr8[w].v;
            unsigned target = (unsigned)t * NCTA;
            while ((int)(ldacq_u32(slot) - target) < 0) { }
        }

        // full h vector straight into registers: 8 x 128-bit gpu-scope loads
        const float* hb = g_hv[t & 1];
        float4 hv0 = ldacq_v4(hb + 0*128 + lane*4);
        float4 hv1 = ldacq_v4(hb + 1*128 + lane*4);
        float4 hv2 = ldacq_v4(hb + 2*128 + lane*4);
        float4 hv3 = ldacq_v4(hb + 3*128 + lane*4);
        float4 hv4 = ldacq_v4(hb + 4*128 + lane*4);
        float4 hv5 = ldacq_v4(hb + 5*128 + lane*4);
        float4 hv6 = ldacq_v4(hb + 6*128 + lane*4);
        float4 hv7 = ldacq_v4(hb + 7*128 + lane*4);
        float hp = ldrelax_f32(hb + unit);          // h[unit] (hot line)
        float gsc = (lane < 3)
                  ? __ldg(gi + (size_t)t * G3 + (size_t)lane * HDIM + unit)
                  : 0.0f;

        unsigned long long ar2 = 0ull, az2 = 0ull, an2 = 0ull;
        #pragma unroll
        for (int c = 0; c < 8; c++) {
            float4 hv = (c==0)?hv0:(c==1)?hv1:(c==2)?hv2:(c==3)?hv3:
                        (c==4)?hv4:(c==5)?hv5:(c==6)?hv6:hv7;
            unsigned long long ha = pack2(hv.x, hv.y);
            unsigned long long hbp = pack2(hv.z, hv.w);
            ar2 = fma2(wr2[c].x, ha, ar2);
            az2 = fma2(wz2[c].x, ha, az2);
            an2 = fma2(wn2[c].x, ha, an2);
            ar2 = fma2(wr2[c].y, hbp, ar2);
            az2 = fma2(wz2[c].y, hbp, az2);
            an2 = fma2(wn2[c].y, hbp, an2);
        }
        float2 fr = unpack2(ar2);
        float2 fz = unpack2(az2);
        float2 fn = unpack2(an2);
        float ar = fr.x + fr.y;
        float az = fz.x + fz.y;
        float an = fn.x + fn.y;
        #pragma unroll
        for (int o = 16; o; o >>= 1) {
            ar += __shfl_xor_sync(0xffffffffu, ar, o);
            az += __shfl_xor_sync(0xffffffffu, az, o);
            an += __shfl_xor_sync(0xffffffffu, an, o);
        }

        float xr = __shfl_sync(0xffffffffu, gsc, 0);
        float xz = __shfl_sync(0xffffffffu, gsc, 1);
        float xn = __shfl_sync(0xffffffffu, gsc, 2);
        float r = fsig(xr + ar + br);
        float z = fsig(xz + az + bz);
        float n = ftanh(xn + r * (an + bn_));
        float hnw = (1.0f - z) * n + z * hp;
        if (lane == 0) {
            g_hv[(t + 1) & 1][unit] = hnw;      // plain store; ordered via bar+red.release
            if (ys) ys[(size_t)t * HDIM + unit] = hnw;
            h_last = hnw;
        }
        __syncthreads();                         // all 8 unit stores before arrivals
        if (tid < 8)
            red_release_add(&g_ctr8[tid].v, 1u);
    }

    if (lane == 0) {
        hfin[unit] = h_last;
        if (hfin2) hfin2[unit] = h_last;
    }
}

// reset: h_0 = 0 in both buffers, all counter replicas = 0
__global__ void zero_state_kernel()
{
    g_hv[0][threadIdx.x] = 0.0f;
    g_hv[1][threadIdx.x] = 0.0f;
    if (threadIdx.x < 8) g_ctr8[threadIdx.x].v = 0u;
}

// ---------------- launch -----------------------------------------------------
extern "C" void kernel_launch(void* const* d_in, const int* in_sizes, int n_in,
                              void* d_out, int out_size)
{
    const int*   idx  = (const int*)  d_in[0];
    const float* E    = (const float*)d_in[1];
    const float* Wih0 = (const float*)d_in[2];
    const float* Whh0 = (const float*)d_in[3];
    const float* bih0 = (const float*)d_in[4];
    const float* bhh0 = (const float*)d_in[5];
    const float* Wih1 = (const float*)d_in[6];
    const float* Whh1 = (const float*)d_in[7];
    const float* bih1 = (const float*)d_in[8];
    const float* bhh1 = (const float*)d_in[9];
    float* out = (float*)d_out;

    float *emb, *gi, *ysv;
    cudaGetSymbolAddress((void**)&emb, g_emb);
    cudaGetSymbolAddress((void**)&gi,  g_gi);
    cudaGetSymbolAddress((void**)&ysv, g_ys);

    // 1) embedding + max-norm
    embed_kernel<<<L_SEQ, 128>>>(idx, E, emb);

    // 2) layer-0 input projection: gi = emb @ Wih0^T + bih0
    gemm_tn<<<dim3(G3/128, L_SEQ/128), 256>>>(emb, Wih0, bih0, gi, L_SEQ, G3, EDIM);

    // 3) layer-0 recurrence -> ys1, h1 (h1 -> out[1024:2048])
    zero_state_kernel<<<1, 1024>>>();
    gru_scan<<<NCTA, 256>>>(Whh0, bhh0, gi, ysv, out + HDIM, nullptr, L_SEQ);

    // 4) layer-1 input projection: gi = ys1 @ Wih1^T + bih1
    gemm_tn<<<dim3(G3/128, L_SEQ/128), 256>>>(ysv, Wih1, bih1, gi, L_SEQ, G3, HDIM);

    // 5) layer-1 recurrence -> h2 (h2 -> out[2048:3072] and ys2[-1] -> out[0:1024])
    zero_state_kernel<<<1, 1024>>>();
    gru_scan<<<NCTA, 256>>>(Whh1, bhh1, gi, nullptr, out + 2*HDIM, out, L_SEQ);
}

// round 8
// speedup vs baseline: 1.1329x; 1.1329x over previous
#include <cuda_runtime.h>
#include <math.h>

#define L_SEQ 4096
#define EDIM  512
#define HDIM  1024
#define G3    3072   // 3*HDIM
#define NCTA  128

// ---------------- scratch (static device globals; no allocation) -------------
__device__ float g_emb[(size_t)L_SEQ * EDIM];          // 8 MB
__device__ float g_gi [(size_t)L_SEQ * G3];            // 50 MB (reused per layer)
__device__ float g_ys [(size_t)L_SEQ * HDIM];          // 16 MB (layer-0 outputs)
__device__ float g_hv[2][HDIM];                        // double-buffered hidden state

// 8 counter replicas, one 128B line each; warp w releases replica w.
struct __align__(128) CtrLine { unsigned v; unsigned pad[31]; };
__device__ CtrLine g_ctr8[8];

// ---------------- memory-model helpers ---------------------------------------
__device__ __forceinline__ unsigned ldacq_u32(const unsigned* p)
{
    unsigned v;
    asm volatile("ld.acquire.gpu.global.b32 %0, [%1];" : "=r"(v) : "l"(p) : "memory");
    return v;
}
__device__ __forceinline__ void red_release_add(unsigned* p, unsigned v)
{
    asm volatile("red.release.gpu.global.add.u32 [%0], %1;" :: "l"(p), "r"(v) : "memory");
}
__device__ __forceinline__ float4 ldacq_v4(const float* p)
{
    float4 v;
    asm volatile("ld.acquire.gpu.global.v4.f32 {%0,%1,%2,%3}, [%4];"
                 : "=f"(v.x), "=f"(v.y), "=f"(v.z), "=f"(v.w) : "l"(p) : "memory");
    return v;
}

// ---------------- packed f32x2 helpers (sm_103a) ------------------------------
__device__ __forceinline__ unsigned long long pack2(float x, float y)
{
    unsigned long long r;
    asm("mov.b64 %0, {%1, %2};" : "=l"(r) : "f"(x), "f"(y));
    return r;
}
__device__ __forceinline__ unsigned long long fma2(unsigned long long a,
                                                   unsigned long long b,
                                                   unsigned long long c)
{
    unsigned long long d;
    asm("fma.rn.f32x2 %0, %1, %2, %3;" : "=l"(d) : "l"(a), "l"(b), "l"(c));
    return d;
}
__device__ __forceinline__ float2 unpack2(unsigned long long v)
{
    float2 f;
    asm("mov.b64 {%0, %1}, %2;" : "=f"(f.x), "=f"(f.y) : "l"(v));
    return f;
}

// fast saturation-safe activations (budget 1e-3; these are ~1e-6)
__device__ __forceinline__ float fsig(float x)
{
    return __fdividef(1.0f, 1.0f + __expf(-x));
}
__device__ __forceinline__ float ftanh(float x)
{
    return 1.0f - __fdividef(2.0f, 1.0f + __expf(2.0f * x));
}

// ---------------- embedding + max-norm --------------------------------------
__global__ void embed_kernel(const int* __restrict__ idx,
                             const float* __restrict__ E,
                             float* __restrict__ emb)
{
    int t = blockIdx.x;
    int id = idx[t];
    const float4* row = (const float4*)(E + (size_t)id * EDIM);
    float4 v = row[threadIdx.x];
    float ss = v.x*v.x + v.y*v.y + v.z*v.z + v.w*v.w;
    #pragma unroll
    for (int o = 16; o; o >>= 1) ss += __shfl_xor_sync(0xffffffffu, ss, o);
    __shared__ float red[4];
    int w = threadIdx.x >> 5;
    if ((threadIdx.x & 31) == 0) red[w] = ss;
    __syncthreads();
    float tot = red[0] + red[1] + red[2] + red[3];
    float scale = fminf(1.0f, 1.0f / fmaxf(sqrtf(tot), 1e-7f));
    v.x *= scale; v.y *= scale; v.z *= scale; v.w *= scale;
    ((float4*)(emb + (size_t)t * EDIM))[threadIdx.x] = v;
}

// ---------------- fp32 GEMM (f32x2 inner): C = A @ B^T + bias ----------------
__global__ void __launch_bounds__(256) gemm_tn(const float* __restrict__ A,
                                               const float* __restrict__ B,
                                               const float* __restrict__ bias,
                                               float* __restrict__ C,
                                               int M, int N, int K)
{
    __shared__ float As[16][128];
    __shared__ float Bs[16][136];

    int tid = threadIdx.x;
    int bm = blockIdx.y * 128;
    int bn = blockIdx.x * 128;
    int tx = tid & 15;
    int ty = tid >> 4;

    unsigned long long acc2[8][4];
    #pragma unroll
    for (int i = 0; i < 8; i++)
        #pragma unroll
        for (int j = 0; j < 4; j++) acc2[i][j] = 0ull;

    const float* Ab = A + (size_t)bm * K;
    const float* Bb = B + (size_t)bn * K;

    for (int k0 = 0; k0 < K; k0 += 16) {
        #pragma unroll
        for (int i = 0; i < 2; i++) {
            int q   = tid + i * 256;
            int row = q >> 2;
            int c4  = q & 3;
            float4 a = *(const float4*)(Ab + (size_t)row * K + k0 + c4 * 4);
            As[c4*4+0][row] = a.x; As[c4*4+1][row] = a.y;
            As[c4*4+2][row] = a.z; As[c4*4+3][row] = a.w;
            float4 b = *(const float4*)(Bb + (size_t)row * K + k0 + c4 * 4);
            Bs[c4*4+0][row] = b.x; Bs[c4*4+1][row] = b.y;
            Bs[c4*4+2][row] = b.z; Bs[c4*4+3][row] = b.w;
        }
        __syncthreads();
        #pragma unroll
        for (int k = 0; k < 16; k++) {
            float4 a0 = *(const float4*)&As[k][ty*8];
            float4 a1 = *(const float4*)&As[k][ty*8+4];
            float4 b0 = *(const float4*)&Bs[k][tx*8];
            float4 b1 = *(const float4*)&Bs[k][tx*8+4];
            float av[8] = {a0.x,a0.y,a0.z,a0.w,a1.x,a1.y,a1.z,a1.w};
            unsigned long long bp[4] = { pack2(b0.x,b0.y), pack2(b0.z,b0.w),
                                         pack2(b1.x,b1.y), pack2(b1.z,b1.w) };
            #pragma unroll
            for (int i = 0; i < 8; i++) {
                unsigned long long ad = pack2(av[i], av[i]);
                #pragma unroll
                for (int j = 0; j < 4; j++)
                    acc2[i][j] = fma2(ad, bp[j], acc2[i][j]);
            }
        }
        __syncthreads();
    }

    float bb[8];
    #pragma unroll
    for (int j = 0; j < 8; j++) bb[j] = bias[bn + tx*8 + j];
    #pragma unroll
    for (int i = 0; i < 8; i++) {
        size_t row = (size_t)(bm + ty*8 + i);
        float2 c0 = unpack2(acc2[i][0]);
        float2 c1 = unpack2(acc2[i][1]);
        float2 c2 = unpack2(acc2[i][2]);
        float2 c3 = unpack2(acc2[i][3]);
        float4 o0 = make_float4(c0.x+bb[0], c0.y+bb[1], c1.x+bb[2], c1.y+bb[3]);
        float4 o1 = make_float4(c2.x+bb[4], c2.y+bb[5], c3.x+bb[6], c3.y+bb[7]);
        *(float4*)(C + row * N + bn + tx*8    ) = o0;
        *(float4*)(C + row * N + bn + tx*8 + 4) = o1;
    }
}

// ---------------- persistent GRU recurrence ----------------------------------
// 128 CTAs x 256 threads. Warp w of CTA b owns unit b*8+w; W_hh in registers
// as f32x2 pairs; h broadcast via smem (one 4KB CTA load). Per step:
//   - tid<24: gi prefetch into smem (independent of sync; overlaps poll)
//   - tid0: acquire-poll SUM of 8 replica counters >= 1024*t ; bar#1
//   - all: one 128-bit ldacq of h slice -> smem ; bar#2
//   - FMA2 chain + xor-shfl reduce + all-lane gate math
//   - lane0: st h' ; red.release to replica w        [NO end-of-step barrier]
// Safety: a warp passes poll(t) only if all 1024 warps released t-1; each
// release is program-ordered after its CTA's bar#2(t-1), i.e. after all that
// CTA's reads of buffer (t-1)&1 -> overwriting parity (t+1)&1 is race-free.
// Barrier-phase aliasing impossible: bar#2(t) fully releases before any warp
// can reach bar#1(t+1) (poll(t+1) requires every warp past bar#2(t)).
__global__ void __launch_bounds__(256, 1) gru_scan(const float* __restrict__ Whh,
                                                   const float* __restrict__ bhh,
                                                   const float* __restrict__ gi,
                                                   float* __restrict__ ys,
                                                   float* __restrict__ hfin,
                                                   float* __restrict__ hfin2,
                                                   int T)
{
    int tid  = threadIdx.x;
    int w    = tid >> 5;
    int lane = tid & 31;
    int b    = blockIdx.x;
    int unit = b * 8 + w;

    const ulonglong2* Wr = (const ulonglong2*)(Whh + (size_t)unit            * HDIM);
    const ulonglong2* Wz = (const ulonglong2*)(Whh + (size_t)(HDIM   + unit) * HDIM);
    const ulonglong2* Wn = (const ulonglong2*)(Whh + (size_t)(2*HDIM + unit) * HDIM);
    ulonglong2 wr2[8], wz2[8], wn2[8];
    #pragma unroll
    for (int c = 0; c < 8; c++) {
        wr2[c] = Wr[c*32 + lane];
        wz2[c] = Wz[c*32 + lane];
        wn2[c] = Wn[c*32 + lane];
    }
    float br  = bhh[unit];
    float bz  = bhh[HDIM   + unit];
    float bn_ = bhh[2*HDIM + unit];

    __shared__ __align__(16) float h_s[HDIM];
    __shared__ float gi_s[24];
    float h_last = 0.0f;

    for (int t = 0; t < T; t++) {
        // gi prefetch (overlaps the poll)
        if (tid < 24)
            gi_s[tid] = gi[(size_t)t * G3 + (size_t)(tid >> 3) * HDIM + b*8 + (tid & 7)];

        // wait: all 1024 warps released step t-1 (8 parallel acquire loads)
        if (tid == 0) {
            unsigned target = (unsigned)t * 1024u;
            for (;;) {
                unsigned s = 0;
                #pragma unroll
                for (int i = 0; i < 8; i++) s += ldacq_u32(&g_ctr8[i].v);
                if ((int)(s - target) >= 0) break;
            }
        }
        __syncthreads();                         // bar#1

        // one 128-bit strong load of h -> smem
        float4 hv = ldacq_v4(&g_hv[t & 1][tid * 4]);
        *(float4*)&h_s[tid * 4] = hv;
        __syncthreads();                         // bar#2

        unsigned long long ar2 = 0ull, az2 = 0ull, an2 = 0ull;
        #pragma unroll
        for (int c = 0; c < 8; c++) {
            ulonglong2 h2 = *(const ulonglong2*)&h_s[c*128 + lane*4];
            ar2 = fma2(wr2[c].x, h2.x, ar2);
            az2 = fma2(wz2[c].x, h2.x, az2);
            an2 = fma2(wn2[c].x, h2.x, an2);
            ar2 = fma2(wr2[c].y, h2.y, ar2);
            az2 = fma2(wz2[c].y, h2.y, az2);
            an2 = fma2(wn2[c].y, h2.y, an2);
        }
        float2 fr = unpack2(ar2);
        float2 fz = unpack2(az2);
        float2 fn = unpack2(an2);
        float ar = fr.x + fr.y;
        float az = fz.x + fz.y;
        float an = fn.x + fn.y;
        #pragma unroll
        for (int o = 16; o; o >>= 1) {
            ar += __shfl_xor_sync(0xffffffffu, ar, o);
            az += __shfl_xor_sync(0xffffffffu, az, o);
            an += __shfl_xor_sync(0xffffffffu, an, o);
        }

        // all lanes compute the gate chain
        float xr = gi_s[w], xz = gi_s[8 + w], xn = gi_s[16 + w];
        float r = fsig(xr + ar + br);
        float z = fsig(xz + az + bz);
        float n = ftanh(xn + r * (an + bn_));
        float hp = h_s[unit];
        float hnw = (1.0f - z) * n + z * hp;
        if (lane == 0) {
            g_hv[(t + 1) & 1][unit] = hnw;          // plain store
            if (ys) ys[(size_t)t * HDIM + unit] = hnw;
            h_last = hnw;
            red_release_add(&g_ctr8[w].v, 1u);      // release covers the store
        }
        // no end-of-step barrier
    }

    if (lane == 0) {
        hfin[unit] = h_last;
        if (hfin2) hfin2[unit] = h_last;
    }
}

// reset: h_0 = 0 in both buffers, all counter replicas = 0
__global__ void zero_state_kernel()
{
    g_hv[0][threadIdx.x] = 0.0f;
    g_hv[1][threadIdx.x] = 0.0f;
    if (threadIdx.x < 8) g_ctr8[threadIdx.x].v = 0u;
}

// ---------------- launch -----------------------------------------------------
extern "C" void kernel_launch(void* const* d_in, const int* in_sizes, int n_in,
                              void* d_out, int out_size)
{
    const int*   idx  = (const int*)  d_in[0];
    const float* E    = (const float*)d_in[1];
    const float* Wih0 = (const float*)d_in[2];
    const float* Whh0 = (const float*)d_in[3];
    const float* bih0 = (const float*)d_in[4];
    const float* bhh0 = (const float*)d_in[5];
    const float* Wih1 = (const float*)d_in[6];
    const float* Whh1 = (const float*)d_in[7];
    const float* bih1 = (const float*)d_in[8];
    const float* bhh1 = (const float*)d_in[9];
    float* out = (float*)d_out;

    float *emb, *gi, *ysv;
    cudaGetSymbolAddress((void**)&emb, g_emb);
    cudaGetSymbolAddress((void**)&gi,  g_gi);
    cudaGetSymbolAddress((void**)&ysv, g_ys);

    // 1) embedding + max-norm
    embed_kernel<<<L_SEQ, 128>>>(idx, E, emb);

    // 2) layer-0 input projection: gi = emb @ Wih0^T + bih0
    gemm_tn<<<dim3(G3/128, L_SEQ/128), 256>>>(emb, Wih0, bih0, gi, L_SEQ, G3, EDIM);

    // 3) layer-0 recurrence -> ys1, h1 (h1 -> out[1024:2048])
    zero_state_kernel<<<1, 1024>>>();
    gru_scan<<<NCTA, 256>>>(Whh0, bhh0, gi, ysv, out + HDIM, nullptr, L_SEQ);

    // 4) layer-1 input projection: gi = ys1 @ Wih1^T + bih1
    gemm_tn<<<dim3(G3/128, L_SEQ/128), 256>>>(ysv, Wih1, bih1, gi, L_SEQ, G3, HDIM);

    // 5) layer-1 recurrence -> h2 (h2 -> out[2048:3072] and ys2[-1] -> out[0:1024])
    zero_state_kernel<<<1, 1024>>>();
    gru_scan<<<NCTA, 256>>>(Whh1, bhh1, gi, nullptr, out + 2*HDIM, out, L_SEQ);
}

// round 9
// speedup vs baseline: 3.6572x; 3.2283x over previous
#include <cuda_runtime.h>
#include <math.h>

#define L_SEQ 4096
#define EDIM  512
#define HDIM  1024
#define G3    3072
#define CHUNK 128
#define NCHUNK (L_SEQ / CHUNK)      // 32
#define L0CTA 64
#define L1CTA 64
#define GEMCTA 20
#define NFUSED (L0CTA + L1CTA + GEMCTA)   // 148 = #SMs -> single wave guaranteed

// ---------------- scratch (static device globals; no allocation) -------------
__device__ float g_emb[(size_t)L_SEQ * EDIM];          // 8 MB
__device__ float g_gi0[(size_t)L_SEQ * G3];            // 50 MB (layer-0 input proj)
__device__ float g_gi1[(size_t)L_SEQ * G3];            // 50 MB (layer-1 input proj)
__device__ float g_ys [(size_t)L_SEQ * HDIM];          // 16 MB (layer-0 outputs)
__device__ float g_h0[2][HDIM];
__device__ float g_h1[2][HDIM];

struct __align__(128) CtrLine { unsigned v; unsigned pad[31]; };
__device__ CtrLine g_ctrA;   // layer-0 step counter   (+64 per step)
__device__ CtrLine g_ctrB;   // gi1 chunk counter      (+20 per chunk)
__device__ CtrLine g_ctrC;   // layer-1 step counter   (+64 per step)

// ---------------- memory-model helpers ---------------------------------------
__device__ __forceinline__ unsigned ldacq_u32(const unsigned* p)
{
    unsigned v;
    asm volatile("ld.acquire.gpu.global.b32 %0, [%1];" : "=r"(v) : "l"(p) : "memory");
    return v;
}
__device__ __forceinline__ void red_release_add(unsigned* p, unsigned v)
{
    asm volatile("red.release.gpu.global.add.u32 [%0], %1;" :: "l"(p), "r"(v) : "memory");
}
__device__ __forceinline__ float4 ldacq_v4(const float* p)
{
    float4 v;
    asm volatile("ld.acquire.gpu.global.v4.f32 {%0,%1,%2,%3}, [%4];"
                 : "=f"(v.x), "=f"(v.y), "=f"(v.z), "=f"(v.w) : "l"(p) : "memory");
    return v;
}

// ---------------- packed f32x2 helpers (sm_103a) ------------------------------
__device__ __forceinline__ unsigned long long pack2(float x, float y)
{
    unsigned long long r;
    asm("mov.b64 %0, {%1, %2};" : "=l"(r) : "f"(x), "f"(y));
    return r;
}
__device__ __forceinline__ unsigned long long fma2(unsigned long long a,
                                                   unsigned long long b,
                                                   unsigned long long c)
{
    unsigned long long d;
    asm("fma.rn.f32x2 %0, %1, %2, %3;" : "=l"(d) : "l"(a), "l"(b), "l"(c));
    return d;
}
__device__ __forceinline__ float2 unpack2(unsigned long long v)
{
    float2 f;
    asm("mov.b64 {%0, %1}, %2;" : "=f"(f.x), "=f"(f.y) : "l"(v));
    return f;
}

__device__ __forceinline__ float fsig(float x)
{
    return __fdividef(1.0f, 1.0f + __expf(-x));
}
__device__ __forceinline__ float ftanh(float x)
{
    return 1.0f - __fdividef(2.0f, 1.0f + __expf(2.0f * x));
}

// ---------------- embedding + max-norm --------------------------------------
__global__ void embed_kernel(const int* __restrict__ idx,
                             const float* __restrict__ E,
                             float* __restrict__ emb)
{
    int t = blockIdx.x;
    int id = idx[t];
    const float4* row = (const float4*)(E + (size_t)id * EDIM);
    float4 v = row[threadIdx.x];
    float ss = v.x*v.x + v.y*v.y + v.z*v.z + v.w*v.w;
    #pragma unroll
    for (int o = 16; o; o >>= 1) ss += __shfl_xor_sync(0xffffffffu, ss, o);
    __shared__ float red[4];
    int w = threadIdx.x >> 5;
    if ((threadIdx.x & 31) == 0) red[w] = ss;
    __syncthreads();
    float tot = red[0] + red[1] + red[2] + red[3];
    float scale = fminf(1.0f, 1.0f / fmaxf(sqrtf(tot), 1e-7f));
    v.x *= scale; v.y *= scale; v.z *= scale; v.w *= scale;
    ((float4*)(emb + (size_t)t * EDIM))[threadIdx.x] = v;
}

// ---------------- double-buffered f32x2 GEMM tile: 128x128, C = A@B^T + bias --
// Ab: 128 rows of A (ld K); Bb: 128 rows of B (ld K); Cb: C + bm*ldc + bn.
__device__ void gemm_tile_db(const float* __restrict__ Ab,
                             const float* __restrict__ Bb,
                             const float* __restrict__ bias,
                             float* __restrict__ Cb,
                             int ldc, int K)
{
    __shared__ float As[2][16][128];
    __shared__ float Bs[2][16][136];
    int tid = threadIdx.x;
    int tx = tid & 15, ty = tid >> 4;

    unsigned long long acc2[8][4];
    #pragma unroll
    for (int i = 0; i < 8; i++)
        #pragma unroll
        for (int j = 0; j < 4; j++) acc2[i][j] = 0ull;

    int q0 = tid,        r0 = q0 >> 2, c0 = q0 & 3;
    int q1 = tid + 256,  r1 = q1 >> 2, c1 = q1 & 3;

    float4 ra0, ra1, rb0, rb1;
    // load k-block 0
    ra0 = *(const float4*)(Ab + (size_t)r0 * K + c0 * 4);
    rb0 = *(const float4*)(Bb + (size_t)r0 * K + c0 * 4);
    ra1 = *(const float4*)(Ab + (size_t)r1 * K + c1 * 4);
    rb1 = *(const float4*)(Bb + (size_t)r1 * K + c1 * 4);
    // store block 0 -> buf 0
    As[0][c0*4+0][r0] = ra0.x; As[0][c0*4+1][r0] = ra0.y; As[0][c0*4+2][r0] = ra0.z; As[0][c0*4+3][r0] = ra0.w;
    Bs[0][c0*4+0][r0] = rb0.x; Bs[0][c0*4+1][r0] = rb0.y; Bs[0][c0*4+2][r0] = rb0.z; Bs[0][c0*4+3][r0] = rb0.w;
    As[0][c1*4+0][r1] = ra1.x; As[0][c1*4+1][r1] = ra1.y; As[0][c1*4+2][r1] = ra1.z; As[0][c1*4+3][r1] = ra1.w;
    Bs[0][c1*4+0][r1] = rb1.x; Bs[0][c1*4+1][r1] = rb1.y; Bs[0][c1*4+2][r1] = rb1.z; Bs[0][c1*4+3][r1] = rb1.w;
    __syncthreads();

    int nb = K / 16;
    for (int kb = 0; kb < nb; kb++) {
        int buf = kb & 1;
        bool more = (kb + 1 < nb);
        if (more) {
            int k0 = (kb + 1) * 16;
            ra0 = *(const float4*)(Ab + (size_t)r0 * K + k0 + c0 * 4);
            rb0 = *(const float4*)(Bb + (size_t)r0 * K + k0 + c0 * 4);
            ra1 = *(const float4*)(Ab + (size_t)r1 * K + k0 + c1 * 4);
            rb1 = *(const float4*)(Bb + (size_t)r1 * K + k0 + c1 * 4);
        }
        #pragma unroll
        for (int k = 0; k < 16; k++) {
            float4 a0 = *(const float4*)&As[buf][k][ty*8];
            float4 a1 = *(const float4*)&As[buf][k][ty*8+4];
            float4 b0 = *(const float4*)&Bs[buf][k][tx*8];
            float4 b1 = *(const float4*)&Bs[buf][k][tx*8+4];
            float av[8] = {a0.x,a0.y,a0.z,a0.w,a1.x,a1.y,a1.z,a1.w};
            unsigned long long bp[4] = { pack2(b0.x,b0.y), pack2(b0.z,b0.w),
                                         pack2(b1.x,b1.y), pack2(b1.z,b1.w) };
            #pragma unroll
            for (int i = 0; i < 8; i++) {
                unsigned long long ad = pack2(av[i], av[i]);
                #pragma unroll
                for (int j = 0; j < 4; j++)
                    acc2[i][j] = fma2(ad, bp[j], acc2[i][j]);
            }
        }
        if (more) {
            int nbuf = (kb + 1) & 1;
            As[nbuf][c0*4+0][r0] = ra0.x; As[nbuf][c0*4+1][r0] = ra0.y; As[nbuf][c0*4+2][r0] = ra0.z; As[nbuf][c0*4+3][r0] = ra0.w;
            Bs[nbuf][c0*4+0][r0] = rb0.x; Bs[nbuf][c0*4+1][r0] = rb0.y; Bs[nbuf][c0*4+2][r0] = rb0.z; Bs[nbuf][c0*4+3][r0] = rb0.w;
            As[nbuf][c1*4+0][r1] = ra1.x; As[nbuf][c1*4+1][r1] = ra1.y; As[nbuf][c1*4+2][r1] = ra1.z; As[nbuf][c1*4+3][r1] = ra1.w;
            Bs[nbuf][c1*4+0][r1] = rb1.x; Bs[nbuf][c1*4+1][r1] = rb1.y; Bs[nbuf][c1*4+2][r1] = rb1.z; Bs[nbuf][c1*4+3][r1] = rb1.w;
            __syncthreads();
        }
    }

    float bb[8];
    #pragma unroll
    for (int j = 0; j < 8; j++) bb[j] = bias[tx*8 + j];
    #pragma unroll
    for (int i = 0; i < 8; i++) {
        size_t row = (size_t)(ty*8 + i);
        float2 e0 = unpack2(acc2[i][0]);
        float2 e1 = unpack2(acc2[i][1]);
        float2 e2 = unpack2(acc2[i][2]);
        float2 e3 = unpack2(acc2[i][3]);
        float4 o0 = make_float4(e0.x+bb[0], e0.y+bb[1], e1.x+bb[2], e1.y+bb[3]);
        float4 o1 = make_float4(e2.x+bb[4], e2.y+bb[5], e3.x+bb[6], e3.y+bb[7]);
        *(float4*)(Cb + row * ldc + tx*8    ) = o0;
        *(float4*)(Cb + row * ldc + tx*8 + 4) = o1;
    }
    __syncthreads();   // smem safe for next tile
}

__global__ void __launch_bounds__(256) gemm_db_kernel(const float* __restrict__ A,
                                                      const float* __restrict__ B,
                                                      const float* __restrict__ bias,
                                                      float* __restrict__ C,
                                                      int N, int K)
{
    int bm = blockIdx.y * 128;
    int bn = blockIdx.x * 128;
    gemm_tile_db(A + (size_t)bm * K, B + (size_t)bn * K, bias + bn,
                 C + (size_t)bm * N + bn, N, K);
}

// ---------------- fused wavefront kernel --------------------------------------
// CTAs [0,64)    : layer-0 scan, 16 units/CTA (2 per warp), ctrA protocol
// CTAs [64,128)  : layer-1 scan, same, ctrC protocol + ctrB chunk gating
// CTAs [128,148) : gi1 GEMM group, consumes ys chunks, releases ctrB
__global__ void __launch_bounds__(256, 1) fused_kernel(
    const float* __restrict__ Whh0, const float* __restrict__ bhh0,
    const float* __restrict__ Whh1, const float* __restrict__ bhh1,
    const float* __restrict__ Wih1, const float* __restrict__ bih1,
    float* __restrict__ out)
{
    int blk = blockIdx.x;
    int tid = threadIdx.x;

    if (blk >= L0CTA + L1CTA) {
        // ---------------- GEMM group ----------------
        int g = blk - (L0CTA + L1CTA);
        for (int ch = 0; ch < NCHUNK; ch++) {
            if (tid == 0) {
                unsigned tgt = 64u * (unsigned)(CHUNK * (ch + 1));
                while ((int)(ldacq_u32(&g_ctrA.v) - tgt) < 0) { }
            }
            __syncthreads();
            for (int tn = g; tn < G3 / 128; tn += GEMCTA) {
                gemm_tile_db(g_ys + (size_t)(ch * CHUNK) * HDIM,
                             Wih1 + (size_t)(tn * 128) * HDIM,
                             bih1 + tn * 128,
                             g_gi1 + (size_t)(ch * CHUNK) * G3 + tn * 128,
                             G3, HDIM);
            }
            __syncthreads();
            if (tid == 0) red_release_add(&g_ctrB.v, 1u);
        }
        return;
    }

    // ---------------- scan roles ----------------
    int layer = (blk >= L0CTA) ? 1 : 0;
    int cb    = layer ? blk - L0CTA : blk;
    int w     = tid >> 5;
    int lane  = tid & 31;
    int u0    = cb * 16 + 2 * w;               // this warp owns units u0, u0+1

    const float* Whh = layer ? Whh1 : Whh0;
    const float* bhh = layer ? bhh1 : bhh0;
    const float* gi  = layer ? g_gi1 : g_gi0;
    unsigned* stepctr = layer ? &g_ctrC.v : &g_ctrA.v;

    ulonglong2 wr2[2][8], wz2[2][8], wn2[2][8];
    float br[2], bz[2], bn_[2];
    #pragma unroll
    for (int j = 0; j < 2; j++) {
        const ulonglong2* Wr = (const ulonglong2*)(Whh + (size_t)(u0+j)            * HDIM);
        const ulonglong2* Wz = (const ulonglong2*)(Whh + (size_t)(HDIM   + u0+j)   * HDIM);
        const ulonglong2* Wn = (const ulonglong2*)(Whh + (size_t)(2*HDIM + u0+j)   * HDIM);
        #pragma unroll
        for (int c = 0; c < 8; c++) {
            wr2[j][c] = Wr[c*32 + lane];
            wz2[j][c] = Wz[c*32 + lane];
            wn2[j][c] = Wn[c*32 + lane];
        }
        br[j]  = bhh[u0+j];
        bz[j]  = bhh[HDIM   + u0+j];
        bn_[j] = bhh[2*HDIM + u0+j];
    }

    __shared__ __align__(16) float h_s[HDIM];
    __shared__ float gi_s[48];
    float hl0 = 0.0f, hl1 = 0.0f;

    for (int t = 0; t < L_SEQ; t++) {
        // L0: prefetch gi before the poll (data already final).
        if (!layer && tid < 48)
            gi_s[tid] = gi[(size_t)t * G3 + (size_t)(tid >> 4) * HDIM + cb*16 + (tid & 15)];

        if (tid == 0) {
            unsigned tgt = 64u * (unsigned)t;
            while ((int)(ldacq_u32(stepctr) - tgt) < 0) { }
            if (layer) {
                unsigned tb = 20u * ((unsigned)(t >> 7) + 1u);
                while ((int)(ldacq_u32(&g_ctrB.v) - tb) < 0) { }
            }
        }
        __syncthreads();                       // bar#1

        // L1: gi only safe after chunk confirmed; ordered for readers by bar#2.
        if (layer && tid < 48)
            gi_s[tid] = gi[(size_t)t * G3 + (size_t)(tid >> 4) * HDIM + cb*16 + (tid & 15)];

        const float* hb = layer ? g_h1[t & 1] : g_h0[t & 1];
        float4 hv = ldacq_v4(hb + tid * 4);
        *(float4*)&h_s[tid * 4] = hv;
        __syncthreads();                       // bar#2

        unsigned long long ar2[2] = {0ull, 0ull}, az2[2] = {0ull, 0ull}, an2[2] = {0ull, 0ull};
        #pragma unroll
        for (int c = 0; c < 8; c++) {
            ulonglong2 h2 = *(const ulonglong2*)&h_s[c*128 + lane*4];
            #pragma unroll
            for (int j = 0; j < 2; j++) {
                ar2[j] = fma2(wr2[j][c].x, h2.x, ar2[j]);
                az2[j] = fma2(wz2[j][c].x, h2.x, az2[j]);
                an2[j] = fma2(wn2[j][c].x, h2.x, an2[j]);
                ar2[j] = fma2(wr2[j][c].y, h2.y, ar2[j]);
                az2[j] = fma2(wz2[j][c].y, h2.y, az2[j]);
                an2[j] = fma2(wn2[j][c].y, h2.y, an2[j]);
            }
        }
        float sr[2], sz[2], sn[2];
        #pragma unroll
        for (int j = 0; j < 2; j++) {
            float2 fr = unpack2(ar2[j]); sr[j] = fr.x + fr.y;
            float2 fz = unpack2(az2[j]); sz[j] = fz.x + fz.y;
            float2 fn = unpack2(an2[j]); sn[j] = fn.x + fn.y;
        }
        #pragma unroll
        for (int o = 16; o; o >>= 1) {
            #pragma unroll
            for (int j = 0; j < 2; j++) {
                sr[j] += __shfl_xor_sync(0xffffffffu, sr[j], o);
                sz[j] += __shfl_xor_sync(0xffffffffu, sz[j], o);
                sn[j] += __shfl_xor_sync(0xffffffffu, sn[j], o);
            }
        }

        float hnw[2];
        #pragma unroll
        for (int j = 0; j < 2; j++) {
            float xr = gi_s[      2*w + j];
            float xz = gi_s[16 +  2*w + j];
            float xn = gi_s[32 +  2*w + j];
            float r = fsig(xr + sr[j] + br[j]);
            float z = fsig(xz + sz[j] + bz[j]);
            float n = ftanh(xn + r * (sn[j] + bn_[j]));
            float hp = h_s[u0 + j];
            hnw[j] = (1.0f - z) * n + z * hp;
        }
        if (lane == 0) {
            float* hout = layer ? g_h1[(t + 1) & 1] : g_h0[(t + 1) & 1];
            *(float2*)&hout[u0] = make_float2(hnw[0], hnw[1]);
            if (!layer)
                *(float2*)&g_ys[(size_t)t * HDIM + u0] = make_float2(hnw[0], hnw[1]);
            hl0 = hnw[0]; hl1 = hnw[1];
        }
        __syncthreads();                       // all stores before arrival
        if (tid == 0)
            red_release_add(stepctr, 1u);
    }

    if (lane == 0) {
        if (!layer) {                          // h1 -> out[1024:2048]
            out[HDIM + u0]     = hl0;
            out[HDIM + u0 + 1] = hl1;
        } else {                               // ys2[-1]=h2 -> out[0:1024]; h2 -> out[2048:3072]
            out[u0]     = hl0;
            out[u0 + 1] = hl1;
            out[2*HDIM + u0]     = hl0;
            out[2*HDIM + u0 + 1] = hl1;
        }
    }
}

// reset: h buffers = 0, counters = 0
__global__ void zero_state_kernel()
{
    g_h0[0][threadIdx.x] = 0.0f;
    g_h0[1][threadIdx.x] = 0.0f;
    g_h1[0][threadIdx.x] = 0.0f;
    g_h1[1][threadIdx.x] = 0.0f;
    if (threadIdx.x == 0) {
        g_ctrA.v = 0u;
        g_ctrB.v = 0u;
        g_ctrC.v = 0u;
    }
}

// ---------------- launch -----------------------------------------------------
extern "C" void kernel_launch(void* const* d_in, const int* in_sizes, int n_in,
                              void* d_out, int out_size)
{
    const int*   idx  = (const int*)  d_in[0];
    const float* E    = (const float*)d_in[1];
    const float* Wih0 = (const float*)d_in[2];
    const float* Whh0 = (const float*)d_in[3];
    const float* bih0 = (const float*)d_in[4];
    const float* bhh0 = (const float*)d_in[5];
    const float* Wih1 = (const float*)d_in[6];
    const float* Whh1 = (const float*)d_in[7];
    const float* bih1 = (const float*)d_in[8];
    const float* bhh1 = (const float*)d_in[9];
    float* out = (float*)d_out;

    float *emb, *gi0;
    cudaGetSymbolAddress((void**)&emb, g_emb);
    cudaGetSymbolAddress((void**)&gi0, g_gi0);

    // 1) embedding + max-norm
    embed_kernel<<<L_SEQ, 128>>>(idx, E, emb);

    // 2) layer-0 input projection: gi0 = emb @ Wih0^T + bih0 (double-buffered GEMM)
    gemm_db_kernel<<<dim3(G3/128, L_SEQ/128), 256>>>(emb, Wih0, bih0, gi0, G3, EDIM);

    // 3) fused wavefront: layer-0 scan || gi1 GEMM || layer-1 scan
    zero_state_kernel<<<1, 1024>>>();
    fused_kernel<<<NFUSED, 256>>>(Whh0, bhh0, Whh1, bhh1, Wih1, bih1, out);
}

// round 10
// speedup vs baseline: 3.7903x; 1.0364x over previous
#include <cuda_runtime.h>
#include <math.h>

#define L_SEQ 4096
#define EDIM  512
#define HDIM  1024
#define G3    3072
#define CHUNK 128
#define NCHUNK (L_SEQ / CHUNK)      // 32
#define L0CTA 64
#define L1CTA 64
#define GEMCTA 20
#define NFUSED (L0CTA + L1CTA + GEMCTA)   // 148 = #SMs -> single wave guaranteed

// ---------------- scratch (static device globals; no allocation) -------------
__device__ float g_emb[(size_t)L_SEQ * EDIM];          // 8 MB
__device__ float g_gi0[(size_t)L_SEQ * G3];            // 50 MB
__device__ float g_gi1[(size_t)L_SEQ * G3];            // 50 MB
__device__ float g_ys [(size_t)L_SEQ * HDIM];          // 16 MB
__device__ float g_h0[2][HDIM];
__device__ float g_h1[2][HDIM];

struct __align__(128) CtrLine { unsigned v; unsigned pad[31]; };
__device__ CtrLine g_ctrA;   // layer-0 step counter  (+64 per step)
__device__ CtrLine g_ctrB;   // gi1 chunk counter     (+20 per chunk)
__device__ CtrLine g_ctrC;   // layer-1 step counter  (+64 per step)
__device__ CtrLine g_ctrD;   // gi0 chunk counter     (+20 per chunk)

// ---------------- memory-model helpers ---------------------------------------
__device__ __forceinline__ unsigned ldacq_u32(const unsigned* p)
{
    unsigned v;
    asm volatile("ld.acquire.gpu.global.b32 %0, [%1];" : "=r"(v) : "l"(p) : "memory");
    return v;
}
__device__ __forceinline__ void red_release_add(unsigned* p, unsigned v)
{
    asm volatile("red.release.gpu.global.add.u32 [%0], %1;" :: "l"(p), "r"(v) : "memory");
}
__device__ __forceinline__ float4 ldacq_v4(const float* p)
{
    float4 v;
    asm volatile("ld.acquire.gpu.global.v4.f32 {%0,%1,%2,%3}, [%4];"
                 : "=f"(v.x), "=f"(v.y), "=f"(v.z), "=f"(v.w) : "l"(p) : "memory");
    return v;
}

// ---------------- packed f32x2 helpers (sm_103a) ------------------------------
__device__ __forceinline__ unsigned long long pack2(float x, float y)
{
    unsigned long long r;
    asm("mov.b64 %0, {%1, %2};" : "=l"(r) : "f"(x), "f"(y));
    return r;
}
__device__ __forceinline__ unsigned long long fma2(unsigned long long a,
                                                   unsigned long long b,
                                                   unsigned long long c)
{
    unsigned long long d;
    asm("fma.rn.f32x2 %0, %1, %2, %3;" : "=l"(d) : "l"(a), "l"(b), "l"(c));
    return d;
}
__device__ __forceinline__ float2 unpack2(unsigned long long v)
{
    float2 f;
    asm("mov.b64 {%0, %1}, %2;" : "=f"(f.x), "=f"(f.y) : "l"(v));
    return f;
}

__device__ __forceinline__ float fsig(float x)
{
    return __fdividef(1.0f, 1.0f + __expf(-x));
}
__device__ __forceinline__ float ftanh(float x)
{
    return 1.0f - __fdividef(2.0f, 1.0f + __expf(2.0f * x));
}

// ---------------- embedding + max-norm --------------------------------------
__global__ void embed_kernel(const int* __restrict__ idx,
                             const float* __restrict__ E,
                             float* __restrict__ emb)
{
    int t = blockIdx.x;
    int id = idx[t];
    const float4* row = (const float4*)(E + (size_t)id * EDIM);
    float4 v = row[threadIdx.x];
    float ss = v.x*v.x + v.y*v.y + v.z*v.z + v.w*v.w;
    #pragma unroll
    for (int o = 16; o; o >>= 1) ss += __shfl_xor_sync(0xffffffffu, ss, o);
    __shared__ float red[4];
    int w = threadIdx.x >> 5;
    if ((threadIdx.x & 31) == 0) red[w] = ss;
    __syncthreads();
    float tot = red[0] + red[1] + red[2] + red[3];
    float scale = fminf(1.0f, 1.0f / fmaxf(sqrtf(tot), 1e-7f));
    v.x *= scale; v.y *= scale; v.z *= scale; v.w *= scale;
    ((float4*)(emb + (size_t)t * EDIM))[threadIdx.x] = v;
}

// ---------------- double-buffered f32x2 GEMM tile: 128x128, C = A@B^T + bias --
__device__ void gemm_tile_db(const float* __restrict__ Ab,
                             const float* __restrict__ Bb,
                             const float* __restrict__ bias,
                             float* __restrict__ Cb,
                             int ldc, int K)
{
    __shared__ float As[2][16][128];
    __shared__ float Bs[2][16][136];
    int tid = threadIdx.x;
    int tx = tid & 15, ty = tid >> 4;

    unsigned long long acc2[8][4];
    #pragma unroll
    for (int i = 0; i < 8; i++)
        #pragma unroll
        for (int j = 0; j < 4; j++) acc2[i][j] = 0ull;

    int q0 = tid,        r0 = q0 >> 2, c0 = q0 & 3;
    int q1 = tid + 256,  r1 = q1 >> 2, c1 = q1 & 3;

    float4 ra0, ra1, rb0, rb1;
    ra0 = *(const float4*)(Ab + (size_t)r0 * K + c0 * 4);
    rb0 = *(const float4*)(Bb + (size_t)r0 * K + c0 * 4);
    ra1 = *(const float4*)(Ab + (size_t)r1 * K + c1 * 4);
    rb1 = *(const float4*)(Bb + (size_t)r1 * K + c1 * 4);
    As[0][c0*4+0][r0] = ra0.x; As[0][c0*4+1][r0] = ra0.y; As[0][c0*4+2][r0] = ra0.z; As[0][c0*4+3][r0] = ra0.w;
    Bs[0][c0*4+0][r0] = rb0.x; Bs[0][c0*4+1][r0] = rb0.y; Bs[0][c0*4+2][r0] = rb0.z; Bs[0][c0*4+3][r0] = rb0.w;
    As[0][c1*4+0][r1] = ra1.x; As[0][c1*4+1][r1] = ra1.y; As[0][c1*4+2][r1] = ra1.z; As[0][c1*4+3][r1] = ra1.w;
    Bs[0][c1*4+0][r1] = rb1.x; Bs[0][c1*4+1][r1] = rb1.y; Bs[0][c1*4+2][r1] = rb1.z; Bs[0][c1*4+3][r1] = rb1.w;
    __syncthreads();

    int nb = K / 16;
    for (int kb = 0; kb < nb; kb++) {
        int buf = kb & 1;
        bool more = (kb + 1 < nb);
        if (more) {
            int k0 = (kb + 1) * 16;
            ra0 = *(const float4*)(Ab + (size_t)r0 * K + k0 + c0 * 4);
            rb0 = *(const float4*)(Bb + (size_t)r0 * K + k0 + c0 * 4);
            ra1 = *(const float4*)(Ab + (size_t)r1 * K + k0 + c1 * 4);
            rb1 = *(const float4*)(Bb + (size_t)r1 * K + k0 + c1 * 4);
        }
        #pragma unroll
        for (int k = 0; k < 16; k++) {
            float4 a0 = *(const float4*)&As[buf][k][ty*8];
            float4 a1 = *(const float4*)&As[buf][k][ty*8+4];
            float4 b0 = *(const float4*)&Bs[buf][k][tx*8];
            float4 b1 = *(const float4*)&Bs[buf][k][tx*8+4];
            float av[8] = {a0.x,a0.y,a0.z,a0.w,a1.x,a1.y,a1.z,a1.w};
            unsigned long long bp[4] = { pack2(b0.x,b0.y), pack2(b0.z,b0.w),
                                         pack2(b1.x,b1.y), pack2(b1.z,b1.w) };
            #pragma unroll
            for (int i = 0; i < 8; i++) {
                unsigned long long ad = pack2(av[i], av[i]);
                #pragma unroll
                for (int j = 0; j < 4; j++)
                    acc2[i][j] = fma2(ad, bp[j], acc2[i][j]);
            }
        }
        if (more) {
            int nbuf = (kb + 1) & 1;
            As[nbuf][c0*4+0][r0] = ra0.x; As[nbuf][c0*4+1][r0] = ra0.y; As[nbuf][c0*4+2][r0] = ra0.z; As[nbuf][c0*4+3][r0] = ra0.w;
            Bs[nbuf][c0*4+0][r0] = rb0.x; Bs[nbuf][c0*4+1][r0] = rb0.y; Bs[nbuf][c0*4+2][r0] = rb0.z; Bs[nbuf][c0*4+3][r0] = rb0.w;
            As[nbuf][c1*4+0][r1] = ra1.x; As[nbuf][c1*4+1][r1] = ra1.y; As[nbuf][c1*4+2][r1] = ra1.z; As[nbuf][c1*4+3][r1] = ra1.w;
            Bs[nbuf][c1*4+0][r1] = rb1.x; Bs[nbuf][c1*4+1][r1] = rb1.y; Bs[nbuf][c1*4+2][r1] = rb1.z; Bs[nbuf][c1*4+3][r1] = rb1.w;
            __syncthreads();
        }
    }

    float bb[8];
    #pragma unroll
    for (int j = 0; j < 8; j++) bb[j] = bias[tx*8 + j];
    #pragma unroll
    for (int i = 0; i < 8; i++) {
        size_t row = (size_t)(ty*8 + i);
        float2 e0 = unpack2(acc2[i][0]);
        float2 e1 = unpack2(acc2[i][1]);
        float2 e2 = unpack2(acc2[i][2]);
        float2 e3 = unpack2(acc2[i][3]);
        float4 o0 = make_float4(e0.x+bb[0], e0.y+bb[1], e1.x+bb[2], e1.y+bb[3]);
        float4 o1 = make_float4(e2.x+bb[4], e2.y+bb[5], e3.x+bb[6], e3.y+bb[7]);
        *(float4*)(Cb + row * ldc + tx*8    ) = o0;
        *(float4*)(Cb + row * ldc + tx*8 + 4) = o1;
    }
    __syncthreads();   // smem safe for next tile; orders stores before release
}

// produce one 128-token chunk of an input projection:
// C[ch*CHUNK .. +128) x G3 tiles, this CTA handles tn = g (+20 if g<4)
__device__ void produce_chunk(int g, const float* A, int K,
                              const float* W, const float* bias,
                              float* C, int ch)
{
    for (int tn = g; tn < G3 / 128; tn += GEMCTA) {
        gemm_tile_db(A + (size_t)(ch * CHUNK) * K,
                     W + (size_t)(tn * 128) * K,
                     bias + tn * 128,
                     C + (size_t)(ch * CHUNK) * G3 + tn * 128,
                     G3, K);
    }
}

// ---------------- fused wavefront kernel --------------------------------------
// CTAs [0,64)    : layer-0 scan (ctrA), gated by ctrD at chunk boundaries
// CTAs [64,128)  : layer-1 scan (ctrC), gated by ctrB at chunk boundaries
// CTAs [128,148) : GEMM group: pre gi0[0..1]; per ch: gi1[ch], gi0[ch+2]
__global__ void __launch_bounds__(256, 1) fused_kernel(
    const float* __restrict__ Whh0, const float* __restrict__ bhh0,
    const float* __restrict__ Whh1, const float* __restrict__ bhh1,
    const float* __restrict__ Wih0, const float* __restrict__ bih0,
    const float* __restrict__ Wih1, const float* __restrict__ bih1,
    float* __restrict__ out)
{
    int blk = blockIdx.x;
    int tid = threadIdx.x;

    if (blk >= L0CTA + L1CTA) {
        // ---------------- GEMM group ----------------
        int g = blk - (L0CTA + L1CTA);
        // prologue: gi0 chunks 0 and 1 (emb ready from previous kernel)
        for (int ch = 0; ch < 2; ch++) {
            produce_chunk(g, g_emb, EDIM, Wih0, bih0, g_gi0, ch);
            if (tid == 0) red_release_add(&g_ctrD.v, 1u);
        }
        for (int ch = 0; ch < NCHUNK; ch++) {
            // wait: L0 finished chunk ch (ys rows ready)
            if (tid == 0) {
                unsigned tgt = 64u * (unsigned)(CHUNK * (ch + 1));
                while ((int)(ldacq_u32(&g_ctrA.v) - tgt) < 0) { }
            }
            __syncthreads();
            produce_chunk(g, g_ys, HDIM, Wih1, bih1, g_gi1, ch);
            if (tid == 0) red_release_add(&g_ctrB.v, 1u);
            if (ch + 2 < NCHUNK) {
                produce_chunk(g, g_emb, EDIM, Wih0, bih0, g_gi0, ch + 2);
                if (tid == 0) red_release_add(&g_ctrD.v, 1u);
            }
        }
        return;
    }

    // ---------------- scan roles ----------------
    int layer = (blk >= L0CTA) ? 1 : 0;
    int cb    = layer ? blk - L0CTA : blk;
    int w     = tid >> 5;
    int lane  = tid & 31;
    int u0    = cb * 16 + 2 * w;               // warp owns units u0, u0+1

    const float* Whh = layer ? Whh1 : Whh0;
    const float* bhh = layer ? bhh1 : bhh0;
    const float* gi  = layer ? g_gi1 : g_gi0;
    unsigned* stepctr  = layer ? &g_ctrC.v : &g_ctrA.v;
    unsigned* chunkctr = layer ? &g_ctrB.v : &g_ctrD.v;

    ulonglong2 wr2[2][8], wz2[2][8], wn2[2][8];
    float br[2], bz[2], bn_[2];
    #pragma unroll
    for (int j = 0; j < 2; j++) {
        const ulonglong2* Wr = (const ulonglong2*)(Whh + (size_t)(u0+j)          * HDIM);
        const ulonglong2* Wz = (const ulonglong2*)(Whh + (size_t)(HDIM   + u0+j) * HDIM);
        const ulonglong2* Wn = (const ulonglong2*)(Whh + (size_t)(2*HDIM + u0+j) * HDIM);
        #pragma unroll
        for (int c = 0; c < 8; c++) {
            wr2[j][c] = Wr[c*32 + lane];
            wz2[j][c] = Wz[c*32 + lane];
            wn2[j][c] = Wn[c*32 + lane];
        }
        br[j]  = bhh[u0+j];
        bz[j]  = bhh[HDIM   + u0+j];
        bn_[j] = bhh[2*HDIM + u0+j];
    }

    __shared__ __align__(16) float h_s[HDIM];
    __shared__ float gi_s[48];
    float hl0 = 0.0f, hl1 = 0.0f;

    for (int t = 0; t < L_SEQ; t++) {
        if (tid == 0) {
            // chunk gate only at chunk boundaries (ctr monotonic -> stays valid)
            if ((t & (CHUNK - 1)) == 0) {
                unsigned tb = (unsigned)GEMCTA * ((unsigned)(t >> 7) + 1u);
                while ((int)(ldacq_u32(chunkctr) - tb) < 0) { }
            }
            unsigned tgt = 64u * (unsigned)t;
            while ((int)(ldacq_u32(stepctr) - tgt) < 0) { }
        }
        __syncthreads();                       // bar#1 (orders gi + h reads)

        if (tid < 48)
            gi_s[tid] = gi[(size_t)t * G3 + (size_t)(tid >> 4) * HDIM + cb*16 + (tid & 15)];

        const float* hb = layer ? g_h1[t & 1] : g_h0[t & 1];
        float4 hv = ldacq_v4(hb + tid * 4);
        *(float4*)&h_s[tid * 4] = hv;
        __syncthreads();                       // bar#2

        unsigned long long ar2[2] = {0ull, 0ull}, az2[2] = {0ull, 0ull}, an2[2] = {0ull, 0ull};
        #pragma unroll
        for (int c = 0; c < 8; c++) {
            ulonglong2 h2 = *(const ulonglong2*)&h_s[c*128 + lane*4];
            #pragma unroll
            for (int j = 0; j < 2; j++) {
                ar2[j] = fma2(wr2[j][c].x, h2.x, ar2[j]);
                az2[j] = fma2(wz2[j][c].x, h2.x, az2[j]);
                an2[j] = fma2(wn2[j][c].x, h2.x, an2[j]);
                ar2[j] = fma2(wr2[j][c].y, h2.y, ar2[j]);
                az2[j] = fma2(wz2[j][c].y, h2.y, az2[j]);
                an2[j] = fma2(wn2[j][c].y, h2.y, an2[j]);
            }
        }
        float sr[2], sz[2], sn[2];
        #pragma unroll
        for (int j = 0; j < 2; j++) {
            float2 fr = unpack2(ar2[j]); sr[j] = fr.x + fr.y;
            float2 fz = unpack2(az2[j]); sz[j] = fz.x + fz.y;
            float2 fn = unpack2(an2[j]); sn[j] = fn.x + fn.y;
        }
        #pragma unroll
        for (int o = 16; o; o >>= 1) {
            #pragma unroll
            for (int j = 0; j < 2; j++) {
                sr[j] += __shfl_xor_sync(0xffffffffu, sr[j], o);
                sz[j] += __shfl_xor_sync(0xffffffffu, sz[j], o);
                sn[j] += __shfl_xor_sync(0xffffffffu, sn[j], o);
            }
        }

        float hnw[2];
        #pragma unroll
        for (int j = 0; j < 2; j++) {
            float xr = gi_s[      2*w + j];
            float xz = gi_s[16 +  2*w + j];
            float xn = gi_s[32 +  2*w + j];
            float r = fsig(xr + sr[j] + br[j]);
            float z = fsig(xz + sz[j] + bz[j]);
            float n = ftanh(xn + r * (sn[j] + bn_[j]));
            float hp = h_s[u0 + j];
            hnw[j] = (1.0f - z) * n + z * hp;
        }
        if (lane == 0) {
            float* hout = layer ? g_h1[(t + 1) & 1] : g_h0[(t + 1) & 1];
            *(float2*)&hout[u0] = make_float2(hnw[0], hnw[1]);
            if (!layer)
                *(float2*)&g_ys[(size_t)t * HDIM + u0] = make_float2(hnw[0], hnw[1]);
            hl0 = hnw[0]; hl1 = hnw[1];
        }
        __syncthreads();                       // all stores before arrival
        if (tid == 0)
            red_release_add(stepctr, 1u);
    }

    if (lane == 0) {
        if (!layer) {                          // h1 -> out[1024:2048]
            out[HDIM + u0]     = hl0;
            out[HDIM + u0 + 1] = hl1;
        } else {                               // ys2[-1]=h2 -> out[0:1024]; h2 -> out[2048:3072]
            out[u0]     = hl0;
            out[u0 + 1] = hl1;
            out[2*HDIM + u0]     = hl0;
            out[2*HDIM + u0 + 1] = hl1;
        }
    }
}

// reset: h buffers = 0, counters = 0
__global__ void zero_state_kernel()
{
    g_h0[0][threadIdx.x] = 0.0f;
    g_h0[1][threadIdx.x] = 0.0f;
    g_h1[0][threadIdx.x] = 0.0f;
    g_h1[1][threadIdx.x] = 0.0f;
    if (threadIdx.x == 0) {
        g_ctrA.v = 0u;
        g_ctrB.v = 0u;
        g_ctrC.v = 0u;
        g_ctrD.v = 0u;
    }
}

// ---------------- launch -----------------------------------------------------
extern "C" void kernel_launch(void* const* d_in, const int* in_sizes, int n_in,
                              void* d_out, int out_size)
{
    const int*   idx  = (const int*)  d_in[0];
    const float* E    = (const float*)d_in[1];
    const float* Wih0 = (const float*)d_in[2];
    const float* Whh0 = (const float*)d_in[3];
    const float* bih0 = (const float*)d_in[4];
    const float* bhh0 = (const float*)d_in[5];
    const float* Wih1 = (const float*)d_in[6];
    const float* Whh1 = (const float*)d_in[7];
    const float* bih1 = (const float*)d_in[8];
    const float* bhh1 = (const float*)d_in[9];
    float* out = (float*)d_out;

    float *emb;
    cudaGetSymbolAddress((void**)&emb, g_emb);

    // 1) embedding + max-norm
    embed_kernel<<<L_SEQ, 128>>>(idx, E, emb);

    // 2) everything else in one fused wavefront kernel
    zero_state_kernel<<<1, 1024>>>();
    fused_kernel<<<NFUSED, 256>>>(Whh0, bhh0, Whh1, bhh1,
                                  Wih0, bih0, Wih1, bih1, out);
}

// round 11
// speedup vs baseline: 3.8129x; 1.0060x over previous
#include <cuda_runtime.h>
#include <math.h>

#define L_SEQ 4096
#define EDIM  512
#define HDIM  1024
#define G3    3072
#define CHUNK 128
#define NCHUNK (L_SEQ / CHUNK)      // 32
#define L0CTA 64
#define L1CTA 64
#define GEMCTA 20
#define NFUSED (L0CTA + L1CTA + GEMCTA)   // 148 = #SMs -> single wave guaranteed

// ---------------- scratch (static device globals; no allocation) -------------
__device__ float g_emb[(size_t)L_SEQ * EDIM];          // 8 MB
__device__ float g_gi0[(size_t)L_SEQ * G3];            // 50 MB
__device__ float g_gi1[(size_t)L_SEQ * G3];            // 50 MB
__device__ float g_ys [(size_t)L_SEQ * HDIM];          // 16 MB
__device__ float g_h0[2][HDIM];
__device__ float g_h1[2][HDIM];

struct __align__(128) CtrLine { unsigned v; unsigned pad[31]; };
__device__ CtrLine g_ctrA;   // layer-0 step counter  (+64 per step)
__device__ CtrLine g_ctrB;   // gi1 chunk counter     (+20 per chunk)
__device__ CtrLine g_ctrC;   // layer-1 step counter  (+64 per step)
__device__ CtrLine g_ctrD;   // gi0 chunk counter     (+20 per chunk)

// ---------------- memory-model helpers ---------------------------------------
__device__ __forceinline__ unsigned ldacq_u32(const unsigned* p)
{
    unsigned v;
    asm volatile("ld.acquire.gpu.global.b32 %0, [%1];" : "=r"(v) : "l"(p) : "memory");
    return v;
}
__device__ __forceinline__ void red_release_add(unsigned* p, unsigned v)
{
    asm volatile("red.release.gpu.global.add.u32 [%0], %1;" :: "l"(p), "r"(v) : "memory");
}
__device__ __forceinline__ float4 ldacq_v4(const float* p)
{
    float4 v;
    asm volatile("ld.acquire.gpu.global.v4.f32 {%0,%1,%2,%3}, [%4];"
                 : "=f"(v.x), "=f"(v.y), "=f"(v.z), "=f"(v.w) : "l"(p) : "memory");
    return v;
}

// ---------------- packed f32x2 helpers (sm_103a) ------------------------------
__device__ __forceinline__ unsigned long long pack2(float x, float y)
{
    unsigned long long r;
    asm("mov.b64 %0, {%1, %2};" : "=l"(r) : "f"(x), "f"(y));
    return r;
}
__device__ __forceinline__ unsigned long long fma2(unsigned long long a,
                                                   unsigned long long b,
                                                   unsigned long long c)
{
    unsigned long long d;
    asm("fma.rn.f32x2 %0, %1, %2, %3;" : "=l"(d) : "l"(a), "l"(b), "l"(c));
    return d;
}
__device__ __forceinline__ float2 unpack2(unsigned long long v)
{
    float2 f;
    asm("mov.b64 {%0, %1}, %2;" : "=f"(f.x), "=f"(f.y) : "l"(v));
    return f;
}

__device__ __forceinline__ float fsig(float x)
{
    return __fdividef(1.0f, 1.0f + __expf(-x));
}
__device__ __forceinline__ float ftanh(float x)
{
    return 1.0f - __fdividef(2.0f, 1.0f + __expf(2.0f * x));
}

// ---------------- embedding + max-norm --------------------------------------
__global__ void embed_kernel(const int* __restrict__ idx,
                             const float* __restrict__ E,
                             float* __restrict__ emb)
{
    int t = blockIdx.x;
    int id = idx[t];
    const float4* row = (const float4*)(E + (size_t)id * EDIM);
    float4 v = row[threadIdx.x];
    float ss = v.x*v.x + v.y*v.y + v.z*v.z + v.w*v.w;
    #pragma unroll
    for (int o = 16; o; o >>= 1) ss += __shfl_xor_sync(0xffffffffu, ss, o);
    __shared__ float red[4];
    int w = threadIdx.x >> 5;
    if ((threadIdx.x & 31) == 0) red[w] = ss;
    __syncthreads();
    float tot = red[0] + red[1] + red[2] + red[3];
    float scale = fminf(1.0f, 1.0f / fmaxf(sqrtf(tot), 1e-7f));
    v.x *= scale; v.y *= scale; v.z *= scale; v.w *= scale;
    ((float4*)(emb + (size_t)t * EDIM))[threadIdx.x] = v;
}

// ---------------- double-buffered f32x2 GEMM tile: 128x128, C = A@B^T + bias --
__device__ void gemm_tile_db(const float* __restrict__ Ab,
                             const float* __restrict__ Bb,
                             const float* __restrict__ bias,
                             float* __restrict__ Cb,
                             int ldc, int K)
{
    __shared__ float As[2][16][128];
    __shared__ float Bs[2][16][136];
    int tid = threadIdx.x;
    int tx = tid & 15, ty = tid >> 4;

    unsigned long long acc2[8][4];
    #pragma unroll
    for (int i = 0; i < 8; i++)
        #pragma unroll
        for (int j = 0; j < 4; j++) acc2[i][j] = 0ull;

    int q0 = tid,        r0 = q0 >> 2, c0 = q0 & 3;
    int q1 = tid + 256,  r1 = q1 >> 2, c1 = q1 & 3;

    float4 ra0, ra1, rb0, rb1;
    ra0 = *(const float4*)(Ab + (size_t)r0 * K + c0 * 4);
    rb0 = *(const float4*)(Bb + (size_t)r0 * K + c0 * 4);
    ra1 = *(const float4*)(Ab + (size_t)r1 * K + c1 * 4);
    rb1 = *(const float4*)(Bb + (size_t)r1 * K + c1 * 4);
    As[0][c0*4+0][r0] = ra0.x; As[0][c0*4+1][r0] = ra0.y; As[0][c0*4+2][r0] = ra0.z; As[0][c0*4+3][r0] = ra0.w;
    Bs[0][c0*4+0][r0] = rb0.x; Bs[0][c0*4+1][r0] = rb0.y; Bs[0][c0*4+2][r0] = rb0.z; Bs[0][c0*4+3][r0] = rb0.w;
    As[0][c1*4+0][r1] = ra1.x; As[0][c1*4+1][r1] = ra1.y; As[0][c1*4+2][r1] = ra1.z; As[0][c1*4+3][r1] = ra1.w;
    Bs[0][c1*4+0][r1] = rb1.x; Bs[0][c1*4+1][r1] = rb1.y; Bs[0][c1*4+2][r1] = rb1.z; Bs[0][c1*4+3][r1] = rb1.w;
    __syncthreads();

    int nb = K / 16;
    for (int kb = 0; kb < nb; kb++) {
        int buf = kb & 1;
        bool more = (kb + 1 < nb);
        if (more) {
            int k0 = (kb + 1) * 16;
            ra0 = *(const float4*)(Ab + (size_t)r0 * K + k0 + c0 * 4);
            rb0 = *(const float4*)(Bb + (size_t)r0 * K + k0 + c0 * 4);
            ra1 = *(const float4*)(Ab + (size_t)r1 * K + k0 + c1 * 4);
            rb1 = *(const float4*)(Bb + (size_t)r1 * K + k0 + c1 * 4);
        }
        #pragma unroll
        for (int k = 0; k < 16; k++) {
            float4 a0 = *(const float4*)&As[buf][k][ty*8];
            float4 a1 = *(const float4*)&As[buf][k][ty*8+4];
            float4 b0 = *(const float4*)&Bs[buf][k][tx*8];
            float4 b1 = *(const float4*)&Bs[buf][k][tx*8+4];
            float av[8] = {a0.x,a0.y,a0.z,a0.w,a1.x,a1.y,a1.z,a1.w};
            unsigned long long bp[4] = { pack2(b0.x,b0.y), pack2(b0.z,b0.w),
                                         pack2(b1.x,b1.y), pack2(b1.z,b1.w) };
            #pragma unroll
            for (int i = 0; i < 8; i++) {
                unsigned long long ad = pack2(av[i], av[i]);
                #pragma unroll
                for (int j = 0; j < 4; j++)
                    acc2[i][j] = fma2(ad, bp[j], acc2[i][j]);
            }
        }
        if (more) {
            int nbuf = (kb + 1) & 1;
            As[nbuf][c0*4+0][r0] = ra0.x; As[nbuf][c0*4+1][r0] = ra0.y; As[nbuf][c0*4+2][r0] = ra0.z; As[nbuf][c0*4+3][r0] = ra0.w;
            Bs[nbuf][c0*4+0][r0] = rb0.x; Bs[nbuf][c0*4+1][r0] = rb0.y; Bs[nbuf][c0*4+2][r0] = rb0.z; Bs[nbuf][c0*4+3][r0] = rb0.w;
            As[nbuf][c1*4+0][r1] = ra1.x; As[nbuf][c1*4+1][r1] = ra1.y; As[nbuf][c1*4+2][r1] = ra1.z; As[nbuf][c1*4+3][r1] = ra1.w;
            Bs[nbuf][c1*4+0][r1] = rb1.x; Bs[nbuf][c1*4+1][r1] = rb1.y; Bs[nbuf][c1*4+2][r1] = rb1.z; Bs[nbuf][c1*4+3][r1] = rb1.w;
            __syncthreads();
        }
    }

    float bb[8];
    #pragma unroll
    for (int j = 0; j < 8; j++) bb[j] = bias[tx*8 + j];
    #pragma unroll
    for (int i = 0; i < 8; i++) {
        size_t row = (size_t)(ty*8 + i);
        float2 e0 = unpack2(acc2[i][0]);
        float2 e1 = unpack2(acc2[i][1]);
        float2 e2 = unpack2(acc2[i][2]);
        float2 e3 = unpack2(acc2[i][3]);
        float4 o0 = make_float4(e0.x+bb[0], e0.y+bb[1], e1.x+bb[2], e1.y+bb[3]);
        float4 o1 = make_float4(e2.x+bb[4], e2.y+bb[5], e3.x+bb[6], e3.y+bb[7]);
        *(float4*)(Cb + row * ldc + tx*8    ) = o0;
        *(float4*)(Cb + row * ldc + tx*8 + 4) = o1;
    }
    __syncthreads();   // smem safe for next tile; orders stores before release
}

// produce one 128-token chunk of an input projection
__device__ void produce_chunk(int g, const float* A, int K,
                              const float* W, const float* bias,
                              float* C, int ch)
{
    for (int tn = g; tn < G3 / 128; tn += GEMCTA) {
        gemm_tile_db(A + (size_t)(ch * CHUNK) * K,
                     W + (size_t)(tn * 128) * K,
                     bias + tn * 128,
                     C + (size_t)(ch * CHUNK) * G3 + tn * 128,
                     G3, K);
    }
}

// ---------------- fused wavefront kernel --------------------------------------
// CTAs [0,64)    : layer-0 scan (ctrA), gated by ctrD at chunk boundaries
// CTAs [64,128)  : layer-1 scan (ctrC), gated by ctrB at chunk boundaries
// CTAs [128,148) : GEMM group: pre gi0[0..1]; per ch: gi1[ch], gi0[ch+2]
__global__ void __launch_bounds__(256, 1) fused_kernel(
    const float* __restrict__ Whh0, const float* __restrict__ bhh0,
    const float* __restrict__ Whh1, const float* __restrict__ bhh1,
    const float* __restrict__ Wih0, const float* __restrict__ bih0,
    const float* __restrict__ Wih1, const float* __restrict__ bih1,
    float* __restrict__ out)
{
    int blk = blockIdx.x;
    int tid = threadIdx.x;

    if (blk >= L0CTA + L1CTA) {
        // ---------------- GEMM group ----------------
        int g = blk - (L0CTA + L1CTA);
        for (int ch = 0; ch < 2; ch++) {
            produce_chunk(g, g_emb, EDIM, Wih0, bih0, g_gi0, ch);
            if (tid == 0) red_release_add(&g_ctrD.v, 1u);
        }
        for (int ch = 0; ch < NCHUNK; ch++) {
            if (tid == 0) {
                unsigned tgt = 64u * (unsigned)(CHUNK * (ch + 1));
                while ((int)(ldacq_u32(&g_ctrA.v) - tgt) < 0) { }
            }
            __syncthreads();
            produce_chunk(g, g_ys, HDIM, Wih1, bih1, g_gi1, ch);
            if (tid == 0) red_release_add(&g_ctrB.v, 1u);
            if (ch + 2 < NCHUNK) {
                produce_chunk(g, g_emb, EDIM, Wih0, bih0, g_gi0, ch + 2);
                if (tid == 0) red_release_add(&g_ctrD.v, 1u);
            }
        }
        return;
    }

    // ---------------- scan roles ----------------
    int layer = (blk >= L0CTA) ? 1 : 0;
    int cb    = layer ? blk - L0CTA : blk;
    int w     = tid >> 5;
    int lane  = tid & 31;
    int u0    = cb * 16 + 2 * w;               // warp owns units u0, u0+1

    const float* Whh = layer ? Whh1 : Whh0;
    const float* bhh = layer ? bhh1 : bhh0;
    const float* gi  = layer ? g_gi1 : g_gi0;
    unsigned* stepctr  = layer ? &g_ctrC.v : &g_ctrA.v;
    unsigned* chunkctr = layer ? &g_ctrB.v : &g_ctrD.v;

    ulonglong2 wr2[2][8], wz2[2][8], wn2[2][8];
    float br[2], bz[2], bn_[2];
    #pragma unroll
    for (int j = 0; j < 2; j++) {
        const ulonglong2* Wr = (const ulonglong2*)(Whh + (size_t)(u0+j)          * HDIM);
        const ulonglong2* Wz = (const ulonglong2*)(Whh + (size_t)(HDIM   + u0+j) * HDIM);
        const ulonglong2* Wn = (const ulonglong2*)(Whh + (size_t)(2*HDIM + u0+j) * HDIM);
        #pragma unroll
        for (int c = 0; c < 8; c++) {
            wr2[j][c] = Wr[c*32 + lane];
            wz2[j][c] = Wz[c*32 + lane];
            wn2[j][c] = Wn[c*32 + lane];
        }
        br[j]  = bhh[u0+j];
        bz[j]  = bhh[HDIM   + u0+j];
        bn_[j] = bhh[2*HDIM + u0+j];
    }

    __shared__ __align__(16) float h_s[HDIM];
    __shared__ float gi_s[48];
    float hl0 = 0.0f, hl1 = 0.0f;

    for (int t = 0; t < L_SEQ; t++) {
        bool boundary = (t & (CHUNK - 1)) == 0;

        // gi prefetch BEFORE the poll when this step's chunk is already
        // confirmed (every non-boundary step): overlaps gi DRAM/L2 latency
        // with the poll + h round-trip. (Monotonic counters: once a chunk
        // gate passed at the boundary step, all later steps of the chunk
        // are safe without re-checking.)
        if (!boundary && tid < 48)
            gi_s[tid] = gi[(size_t)t * G3 + (size_t)(tid >> 4) * HDIM + cb*16 + (tid & 15)];

        if (tid == 0) {
            if (boundary) {
                unsigned tb = (unsigned)GEMCTA * ((unsigned)(t >> 7) + 1u);
                while ((int)(ldacq_u32(chunkctr) - tb) < 0) { }
            }
            unsigned tgt = 64u * (unsigned)t;
            while ((int)(ldacq_u32(stepctr) - tgt) < 0) { }
        }
        __syncthreads();                       // bar#1

        // boundary steps: gi only safe after the chunk gate (ordered by bar#1;
        // visible to consumers via bar#2)
        if (boundary && tid < 48)
            gi_s[tid] = gi[(size_t)t * G3 + (size_t)(tid >> 4) * HDIM + cb*16 + (tid & 15)];

        const float* hb = layer ? g_h1[t & 1] : g_h0[t & 1];
        float4 hv = ldacq_v4(hb + tid * 4);
        *(float4*)&h_s[tid * 4] = hv;
        __syncthreads();                       // bar#2

        unsigned long long ar2[2] = {0ull, 0ull}, az2[2] = {0ull, 0ull}, an2[2] = {0ull, 0ull};
        #pragma unroll
        for (int c = 0; c < 8; c++) {
            ulonglong2 h2 = *(const ulonglong2*)&h_s[c*128 + lane*4];
            #pragma unroll
            for (int j = 0; j < 2; j++) {
                ar2[j] = fma2(wr2[j][c].x, h2.x, ar2[j]);
                az2[j] = fma2(wz2[j][c].x, h2.x, az2[j]);
                an2[j] = fma2(wn2[j][c].x, h2.x, an2[j]);
                ar2[j] = fma2(wr2[j][c].y, h2.y, ar2[j]);
                az2[j] = fma2(wz2[j][c].y, h2.y, az2[j]);
                an2[j] = fma2(wn2[j][c].y, h2.y, an2[j]);
            }
        }
        float sr[2], sz[2], sn[2];
        #pragma unroll
        for (int j = 0; j < 2; j++) {
            float2 fr = unpack2(ar2[j]); sr[j] = fr.x + fr.y;
            float2 fz = unpack2(az2[j]); sz[j] = fz.x + fz.y;
            float2 fn = unpack2(an2[j]); sn[j] = fn.x + fn.y;
        }
        #pragma unroll
        for (int o = 16; o; o >>= 1) {
            #pragma unroll
            for (int j = 0; j < 2; j++) {
                sr[j] += __shfl_xor_sync(0xffffffffu, sr[j], o);
                sz[j] += __shfl_xor_sync(0xffffffffu, sz[j], o);
                sn[j] += __shfl_xor_sync(0xffffffffu, sn[j], o);
            }
        }

        float hnw[2];
        #pragma unroll
        for (int j = 0; j < 2; j++) {
            float xr = gi_s[      2*w + j];
            float xz = gi_s[16 +  2*w + j];
            float xn = gi_s[32 +  2*w + j];
            float r = fsig(xr + sr[j] + br[j]);
            float z = fsig(xz + sz[j] + bz[j]);
            float n = ftanh(xn + r * (sn[j] + bn_[j]));
            float hp = h_s[u0 + j];
            hnw[j] = (1.0f - z) * n + z * hp;
        }
        if (lane == 0) {
            float* hout = layer ? g_h1[(t + 1) & 1] : g_h0[(t + 1) & 1];
            *(float2*)&hout[u0] = make_float2(hnw[0], hnw[1]);
            if (!layer)
                *(float2*)&g_ys[(size_t)t * HDIM + u0] = make_float2(hnw[0], hnw[1]);
            hl0 = hnw[0]; hl1 = hnw[1];
        }
        __syncthreads();                       // all stores before arrival
        if (tid == 0)
            red_release_add(stepctr, 1u);
    }

    if (lane == 0) {
        if (!layer) {                          // h1 -> out[1024:2048]
            out[HDIM + u0]     = hl0;
            out[HDIM + u0 + 1] = hl1;
        } else {                               // ys2[-1]=h2 -> out[0:1024]; h2 -> out[2048:3072]
            out[u0]     = hl0;
            out[u0 + 1] = hl1;
            out[2*HDIM + u0]     = hl0;
            out[2*HDIM + u0 + 1] = hl1;
        }
    }
}

// reset: h buffers = 0, counters = 0
__global__ void zero_state_kernel()
{
    g_h0[0][threadIdx.x] = 0.0f;
    g_h0[1][threadIdx.x] = 0.0f;
    g_h1[0][threadIdx.x] = 0.0f;
    g_h1[1][threadIdx.x] = 0.0f;
    if (threadIdx.x == 0) {
        g_ctrA.v = 0u;
        g_ctrB.v = 0u;
        g_ctrC.v = 0u;
        g_ctrD.v = 0u;
    }
}

// ---------------- launch -----------------------------------------------------
extern "C" void kernel_launch(void* const* d_in, const int* in_sizes, int n_in,
                              void* d_out, int out_size)
{
    const int*   idx  = (const int*)  d_in[0];
    const float* E    = (const float*)d_in[1];
    const float* Wih0 = (const float*)d_in[2];
    const float* Whh0 = (const float*)d_in[3];
    const float* bih0 = (const float*)d_in[4];
    const float* bhh0 = (const float*)d_in[5];
    const float* Wih1 = (const float*)d_in[6];
    const float* Whh1 = (const float*)d_in[7];
    const float* bih1 = (const float*)d_in[8];
    const float* bhh1 = (const float*)d_in[9];
    float* out = (float*)d_out;

    float *emb;
    cudaGetSymbolAddress((void**)&emb, g_emb);

    // 1) embedding + max-norm
    embed_kernel<<<L_SEQ, 128>>>(idx, E, emb);

    // 2) everything else in one fused wavefront kernel
    zero_state_kernel<<<1, 1024>>>();
    fused_kernel<<<NFUSED, 256>>>(Whh0, bhh0, Whh1, bhh1,
                                  Wih0, bih0, Wih1, bih1, out);
}